// round 6
// baseline (speedup 1.0000x reference)
#include <cuda_runtime.h>
#include <math.h>

#define BB 32
#define VV 518
#define SS 2048
#define BV (BB*VV)
#define NTOK (BB*SS)
#define GROUPS 8
#define BPG 32                 // blocks per group (per batch)
#define ROUNDS (BB/GROUPS)     // 4
#define NBLK (GROUPS*BPG)      // 256 <= 296 resident at 2/SM: single wave
#define NT 512                 // threads per block
#define CPB (SS/BPG)           // 64 columns per block in phase 2
#define ROWBYTES (SS*4)

// Persistent scratch (allocations forbidden). All reset by k_init each launch.
__device__ double g_sum_nll;
__device__ double g_sum_mask;
__device__ unsigned int g_done;
__device__ unsigned int g_arrive[BB];
__device__ float  g_c[BV];
__device__ int    g_t64;

// ---------------------------------------------------------------------------
// Init: zero all counters/sums, detect target dtype (odd 32-bit words all
// zero over 64 entries <=> little-endian int64 with values < 518).
// ---------------------------------------------------------------------------
__global__ void k_init(const int* __restrict__ t32) {
    __shared__ int nz;
    if (threadIdx.x == 0) { nz = 0; g_sum_nll = 0.0; g_sum_mask = 0.0; g_done = 0u; }
    if (threadIdx.x < BB) g_arrive[threadIdx.x] = 0u;
    __syncthreads();
    if (threadIdx.x < 64 && t32[threadIdx.x * 2 + 1] != 0) atomicOr(&nz, 1);
    __syncthreads();
    if (threadIdx.x == 0) g_t64 = nz ? 0 : 1;
}

// per-element update for 2 columns
#define ACC2(X2, C, V)                                             \
    do {                                                           \
        sum0 += __expf((X2).x);  sum1 += __expf((X2).y);           \
        float _a = (X2).x - (C), _b = (X2).y - (C);                \
        if (_a > best0) { best0 = _a; bv0 = (V); }                 \
        if (_b > best1) { best1 = _b; bv1 = (V); }                 \
    } while (0)

// ---------------------------------------------------------------------------
// Fused kernel. Group g (32 blocks) processes batch b = 8r+g in round r:
//   Phase 1: 512 warps -> one warp per row, LSE over S (DRAM read, 4.25MB).
//   Soft barrier across the 32 blocks (all blocks resident: grid 256, 2/SM).
//   Phase 2: same 32 blocks re-read batch b column-wise -> L2 hits (reuse
//   distance = 8 concurrent batches x 4.25MB = 34MB << 126MB L2).
// Each block: 64 s-columns, 16 warps split V, 2 columns per lane (float2).
// ---------------------------------------------------------------------------
__global__ __launch_bounds__(NT, 2)
void k_main(const float* __restrict__ X, const void* __restrict__ tptr,
            float* __restrict__ out) {
    __shared__ float sc[VV];
    __shared__ float s_sum[16][CPB];
    __shared__ float s_best[16][CPB];
    __shared__ int   s_bv[16][CPB];
    __shared__ double s_red[4];

    const int tid = threadIdx.x, w = tid >> 5, lane = tid & 31;
    const int g = blockIdx.x >> 5;       // group 0..7
    const int j = blockIdx.x & 31;       // block-in-group 0..31
    const int gw = j * 16 + w;           // 0..511 global warp-in-group
    // phase-2 v-range: warps 0..5 get 33 rows, 6..15 get 32 (6*33+10*32=518)
    const int vlo = w * 32 + min(w, 6);
    const int vhi = vlo + ((w < 6) ? 33 : 32);
    const int s0 = j * CPB;

    double acc_n = 0.0, acc_m = 0.0;

    for (int r = 0; r < ROUNDS; r++) {
        const int b = r * GROUPS + g;
        const float* Xb = X + (size_t)b * VV * SS;

        // ---- Phase 1: row LSE, one warp per row (+6 warps take a 2nd row)
        for (int rep = 0; rep < 2; rep++) {
            int v = gw + rep * 512;
            if (v >= VV) break;
            const float4* rowp = (const float4*)(Xb + (size_t)v * SS);
            float a0 = 0.f, a1 = 0.f, a2 = 0.f, a3 = 0.f;
#pragma unroll 4
            for (int i = lane; i < SS/4; i += 32) {
                float4 x = rowp[i];
                a0 += __expf(x.x); a1 += __expf(x.y);
                a2 += __expf(x.z); a3 += __expf(x.w);
            }
            float a = (a0 + a1) + (a2 + a3);
#pragma unroll
            for (int o = 16; o; o >>= 1) a += __shfl_xor_sync(0xffffffffu, a, o);
            if (lane == 0) g_c[b * VV + v] = __logf(a);
        }

        // ---- soft barrier over the 32 blocks of this group (all resident)
        __threadfence();
        __syncthreads();
        if (tid == 0) {
            atomicAdd(&g_arrive[b], 1u);
            while (atomicAdd(&g_arrive[b], 0u) < BPG) __nanosleep(64);
        }
        __syncthreads();

        // ---- Phase 2: column pass over this block's 64 s-positions (L2-hot)
        for (int i = tid; i < VV; i += NT) sc[i] = __ldcg(&g_c[b * VV + i]);
        __syncthreads();

        float sum0 = 0.f, sum1 = 0.f;
        float best0 = -INFINITY, best1 = -INFINITY;
        int bv0 = 0, bv1 = 0;

        const char* p = (const char*)Xb + (size_t)vlo * ROWBYTES
                      + (size_t)(s0 + lane * 2) * 4;
        int v = vlo;
        for (; v + 4 <= vhi; v += 4, p += 4 * ROWBYTES) {
            float2 x0 = *(const float2*)(p);
            float2 x1 = *(const float2*)(p + ROWBYTES);
            float2 x2 = *(const float2*)(p + 2 * ROWBYTES);
            float2 x3 = *(const float2*)(p + 3 * ROWBYTES);
            float c0 = sc[v], c1 = sc[v+1], c2 = sc[v+2], c3 = sc[v+3];
            ACC2(x0, c0, v);
            ACC2(x1, c1, v + 1);
            ACC2(x2, c2, v + 2);
            ACC2(x3, c3, v + 3);
        }
        for (; v < vhi; v++, p += ROWBYTES) {
            float2 x0 = *(const float2*)(p);
            float c0 = sc[v];
            ACC2(x0, c0, v);
        }

        {
            int j0 = lane * 2;
            s_sum[w][j0]  = sum0;  s_sum[w][j0+1]  = sum1;
            s_best[w][j0] = best0; s_best[w][j0+1] = best1;
            s_bv[w][j0]   = bv0;   s_bv[w][j0+1]   = bv1;
        }
        __syncthreads();

        if (tid < CPB) {
            const int jj = tid;
            int tgt;
            {
                int idx = b * SS + s0 + jj;
                if (g_t64) tgt = (int)((const long long*)tptr)[idx];
                else       tgt = ((const int*)tptr)[idx];
            }
            float txt = Xb[(size_t)tgt * SS + s0 + jj];

            float tsum = 0.f, tbest = -INFINITY;
            int tbv = 0;
#pragma unroll
            for (int c = 0; c < 16; c++) {        // ascending = first-max ties
                tsum += s_sum[c][jj];
                if (s_best[c][jj] > tbest) { tbest = s_best[c][jj]; tbv = s_bv[c][jj]; }
            }
            float nll = __logf(tsum) - txt;

            int pt = (tbv < 128) ? 0 : (tbv < 289) ? 1 : (tbv < 390) ? 2 : 3;
            int tt = (tgt < 128) ? 0 : (tgt < 289) ? 1 : (tgt < 390) ? 2 : 3;
            float mask;
            if (pt != tt) {
                mask = 1.0f;
            } else if (pt == 0) {
                mask = 0.5f;
            } else {
                float denom = (pt == 1) ? 160.f : (pt == 2) ? 100.f : 128.f;
                mask = 0.5f * fabsf((float)(tbv - tgt)) / denom;
            }

            double nd = (double)nll, md = (double)mask;
#pragma unroll
            for (int o = 16; o; o >>= 1) {
                nd += __shfl_xor_sync(0xffffffffu, nd, o);
                md += __shfl_xor_sync(0xffffffffu, md, o);
            }
            if (lane == 0) { s_red[w] = nd; s_red[2 + w] = md; }
        }
        __syncthreads();
        if (tid == 0) {
            acc_n += s_red[0] + s_red[1];
            acc_m += s_red[2] + s_red[3];
        }
        __syncthreads();   // smem reuse across rounds
    }

    if (tid == 0) {
        atomicAdd(&g_sum_nll, acc_n);
        atomicAdd(&g_sum_mask, acc_m);
        __threadfence();
        unsigned int done = atomicAdd(&g_done, 1u);
        if (done == NBLK - 1) {
            double nm = g_sum_nll / (double)NTOK;
            double mm = g_sum_mask / (double)NTOK;
            out[0] = (float)(nm * (1.0 + mm));
        }
    }
}

extern "C" void kernel_launch(void* const* d_in, const int* in_sizes, int n_in,
                              void* d_out, int out_size) {
    const float* X   = (const float*)d_in[0];
    const void*  tgt = d_in[1];
    float* out = (float*)d_out;

    k_init<<<1, 128>>>((const int*)tgt);
    k_main<<<NBLK, NT>>>(X, tgt, out);
}